// round 8
// baseline (speedup 1.0000x reference)
#include <cuda_runtime.h>
#include <cuda_bf16.h>
#include <cstdint>

// Problem constants (H=W=256, SMALL=8, LARGE=16, B=2)
#define HW      65536
#define NB      2
#define WNUM    1024
#define S2      64
#define L2      256
#define NTILE   (WNUM*NB)     // 2048
#define NBLK    1024          // single wave at occ 7 (148*7 = 1036)
#define NCORRB  256           // blocks that also do corr
#define K1      26            // bulk iters for corr blocks
#define K2      34            // bulk iters for plain blocks
// 256*256*26 + 768*256*34 = 1703936 + 6684672 = 8388608 float4 = all of P
#define CORR_REGION (NCORRB * 256 * K1)   // 1703936

__device__ int    g_partner[NB * HW];   // 512 KB (L2-resident)
__device__ float2 g_corr[NTILE];        // {nll_sum/c_num, absd_correction}
__device__ float  g_bulk[NBLK];
__device__ int    g_sync1;              // scatter counter (zero-init, rearmed)
__device__ int    g_ticket;             // completion ticket (zero-init, rearmed)

__device__ __forceinline__ float warp_sum(float v) {
    #pragma unroll
    for (int o = 16; o > 0; o >>= 1) v += __shfl_down_sync(0xFFFFFFFFu, v, o);
    return v;
}

// ---------------------------------------------------------------------------
// Single fused kernel, single wave.
//  ALL blocks: scatter 128 entries -> arrive on counter (no wait)
//  corr blocks (0..255): K1 bulk iters -> wait counter==NBLK (long drained)
//      -> per-warp tile corrections (8 tiles/block)
//  plain blocks (256..1023): K2 bulk iters, never wait
//  last ticket: fixed-order final combine, writes out, rearms counters
// ---------------------------------------------------------------------------
__global__ __launch_bounds__(256, 7)
void k_all(const float4* __restrict__ P4,
           const int*    __restrict__ index_r,
           const int*    __restrict__ lw_abs,
           float*        __restrict__ out) {
    const int bid  = blockIdx.x;
    const int tid  = threadIdx.x;
    const int lane = tid & 31;
    const int wrp  = tid >> 5;
    const float* Pf = (const float*)P4;

    // ---- phase 0: scatter slice (128 entries/block over 1024 blocks) ----
    if (tid < 128) {
        int e    = bid * 128 + tid;            // 0..131071 covers NB*HW
        int b    = e >> 16;
        int j    = e & (HW - 1);
        int idx0 = index_r[(b * 2 + 0) * HW + j];
        int idx1 = index_r[(b * 2 + 1) * HW + j];
        g_partner[b * HW + idx1] = idx0;
    }
    __threadfence();
    __syncthreads();
    if (tid == 0) atomicAdd(&g_sync1, 1);      // arrive; only corr blocks wait

    float a0 = 0.f, a1 = 0.f;                  // bulk accumulators

    if (bid < NCORRB) {
        // ---- bulk share first (hides everyone's scatter latency) ----
        const int base = bid * 256 + tid;      // region [0, CORR_REGION)
        #pragma unroll 4
        for (int k = 0; k < K1; k++) {
            float4 p = __ldcs(P4 + base + k * (NCORRB * 256));
            a0 += p.x + p.y;
            a1 += p.z + p.w;
        }

        // ---- wait for all scatters (long since drained) ----
        if (tid == 0) {
            while (*((volatile int*)&g_sync1) < NBLK) { }
        }
        __syncthreads();
        __threadfence();

        // ---- per-warp tile corrections (tile = bid*8 + warp) ----
        const int tile = bid * 8 + wrp;
        const int w    = tile >> 1;
        const int b    = tile & 1;
        const int r0   = (w >> 5) << 3;
        const int c0   = (w & 31) << 3;
        const float* Pt = Pf + (size_t)tile * (S2 * L2);

        float absd = 0.f, nll = 0.f;
        int   cnt  = 0;
        #pragma unroll
        for (int k = 0; k < 8; k++) {
            int l  = lane + 32 * k;
            int lw = __ldg(lw_abs + w * L2 + l);
            int v  = g_partner[b * HW + lw];             // plw
            int i  = (v >> 8) - r0;
            int j  = (v & 255) - c0;
            if ((unsigned)i < 8u && (unsigned)j < 8u && !(v == 0 && lw == 0)) {
                float p = __ldg(Pt + (i * 8 + j) * L2 + l);
                absd += 1.f - 2.f * p;                   // |p-1| - p
                nll  -= __logf(fminf(fmaxf(p, 1e-6f), 1.f - 1e-6f));
                cnt++;
            }
        }
        float cntf = (float)cnt;
        absd = warp_sum(absd);
        nll  = warp_sum(nll);
        cntf = warp_sum(cntf);
        if (lane == 0) g_corr[tile] = make_float2(nll / cntf, absd);
        a0 += 0.f;                                       // keep absd separate:
        // fold absd into this block's bulk partial deterministically:
        if (lane == 0) a1 += absd;                       // one lane per warp
    } else {
        // ---- plain block: bulk only, never waits ----
        const int base = CORR_REGION + (bid - NCORRB) * 256 + tid;
        #pragma unroll 4
        for (int k = 0; k < K2; k++) {
            float4 p = __ldcs(P4 + base + k * ((NBLK - NCORRB) * 256));
            a0 += p.x + p.y;
            a1 += p.z + p.w;
        }
    }
    float acc = a0 + a1;

    // ---- block reduction -> g_bulk, ticket ----
    acc = warp_sum(acc);
    __shared__ float red[8];
    __shared__ bool  s_last;
    if (lane == 0) red[wrp] = acc;
    __syncthreads();
    if (wrp == 0) {
        float a = (lane < 8) ? red[lane] : 0.f;
        #pragma unroll
        for (int o = 4; o > 0; o >>= 1) a += __shfl_down_sync(0xFFFFFFFFu, a, o);
        if (lane == 0) {
            g_bulk[bid] = a;
            __threadfence();
            int t = atomicAdd(&g_ticket, 1);
            s_last = (t == NBLK - 1);
        }
    }
    __syncthreads();

    // ---- final fixed-order combine (deterministic) ----
    if (s_last) {
        float sumP = 0.f, sumR = 0.f;
        #pragma unroll
        for (int i = tid; i < NBLK; i += 256) sumP += g_bulk[i];
        #pragma unroll
        for (int i = tid; i < NTILE; i += 256) sumR += g_corr[i].x;
        sumP = warp_sum(sumP);
        sumR = warp_sum(sumR);
        __shared__ float sp[8], sr[8];
        if (lane == 0) { sp[wrp] = sumP; sr[wrp] = sumR; }
        __syncthreads();
        if (wrp == 0) {
            float p = (lane < 8) ? sp[lane] : 0.f;
            float r = (lane < 8) ? sr[lane] : 0.f;
            #pragma unroll
            for (int o = 4; o > 0; o >>= 1) {
                p += __shfl_down_sync(0xFFFFFFFFu, p, o);
                r += __shfl_down_sync(0xFFFFFFFFu, r, o);
            }
            if (lane == 0) {
                out[0] = r / (float)NTILE;                        // l_cm
                out[1] = p / (float)((size_t)NTILE * S2 * L2);    // l_c
                g_ticket = 0;                                     // rearm
                g_sync1  = 0;
            }
        }
    }
}

// ---------------------------------------------------------------------------
// Launch.  Inputs: [0] P f32, [1] index_r i32, [2] sw_abs i32, [3] lw_abs i32.
// ---------------------------------------------------------------------------
extern "C" void kernel_launch(void* const* d_in, const int* in_sizes, int n_in,
                              void* d_out, int out_size) {
    const float4* P4     = (const float4*)d_in[0];
    const int*    idxr   = (const int*)d_in[1];
    const int*    lw_abs = (const int*)d_in[3];
    float*        out    = (float*)d_out;

    k_all<<<NBLK, 256>>>(P4, idxr, lw_abs, out);
}